// round 1
// baseline (speedup 1.0000x reference)
#include <cuda_runtime.h>

// NeuralEmbeddingLayer: out[b,t,h] = (sum_c W[d[b],h,c]*f[b,t,c] + bias[d[b]])*32 + pos[ts[b,t],h]
// B=32, T=1024, C=512, H=1024, N_DATES=64, MAX_F=2048. SCALE = sqrt(H) = 32.

#define Bb 32
#define Tt 1024
#define Cc 512
#define Hh 1024
#define SCALE_F 32.0f

#define BM 128
#define BN 64
#define BK 32
// 256 threads: 16 (n) x 16 (m), each thread 8(m) x 4(n) outputs

__global__ __launch_bounds__(256, 2)
void embed_kernel(const float* __restrict__ features,   // [B,T,C]
                  const int*   __restrict__ ts,         // [B,T]
                  const int*   __restrict__ date_idx,   // [B]
                  const float* __restrict__ W,          // [N_DATES,H,C]
                  const float* __restrict__ bias,       // [N_DATES]
                  const float* __restrict__ pos,        // [MAX_F,H]
                  float*       __restrict__ out)        // [B,T,H]
{
    __shared__ float As[BK][BM];   // K-transposed A tile
    __shared__ float Bs[BK][BN];   // K-transposed B tile
    __shared__ int   tsS[BM];

    const int b   = blockIdx.z;
    const int t0  = blockIdx.y * BM;
    const int h0  = blockIdx.x * BN;
    const int tid = threadIdx.x;
    const int tx  = tid & 15;   // n
    const int ty  = tid >> 4;   // m

    const int d = date_idx[b];
    const float* Ag = features + ((long)b * Tt + t0) * Cc;
    const float* Bg = W + ((long)d * Hh + h0) * Cc;

    if (tid < BM) tsS[tid] = ts[b * Tt + t0 + tid];

    float acc[8][4];
    #pragma unroll
    for (int i = 0; i < 8; i++)
        #pragma unroll
        for (int j = 0; j < 4; j++)
            acc[i][j] = 0.0f;

    for (int k0 = 0; k0 < Cc; k0 += BK) {
        // Load A tile: 128 rows x 32 cols = 1024 float4 / 256 threads = 4 each
        #pragma unroll
        for (int it = 0; it < 4; it++) {
            int idx = tid + it * 256;          // 0..1023
            int row = idx & 127;
            int c4  = idx >> 7;                // 0..7
            float4 v = *(const float4*)(Ag + (long)row * Cc + k0 + c4 * 4);
            As[c4 * 4 + 0][row] = v.x;
            As[c4 * 4 + 1][row] = v.y;
            As[c4 * 4 + 2][row] = v.z;
            As[c4 * 4 + 3][row] = v.w;
        }
        // Load B tile: 64 rows x 32 cols = 512 float4 / 256 threads = 2 each
        #pragma unroll
        for (int it = 0; it < 2; it++) {
            int idx = tid + it * 256;          // 0..511
            int row = idx & 63;
            int c4  = idx >> 6;                // 0..7
            float4 v = *(const float4*)(Bg + (long)row * Cc + k0 + c4 * 4);
            Bs[c4 * 4 + 0][row] = v.x;
            Bs[c4 * 4 + 1][row] = v.y;
            Bs[c4 * 4 + 2][row] = v.z;
            Bs[c4 * 4 + 3][row] = v.w;
        }
        __syncthreads();

        #pragma unroll
        for (int kk = 0; kk < BK; kk++) {
            float a[8], bf[4];
            *(float4*)&a[0] = *(const float4*)&As[kk][ty * 8];
            *(float4*)&a[4] = *(const float4*)&As[kk][ty * 8 + 4];
            *(float4*)&bf[0] = *(const float4*)&Bs[kk][tx * 4];
            #pragma unroll
            for (int i = 0; i < 8; i++)
                #pragma unroll
                for (int j = 0; j < 4; j++)
                    acc[i][j] = fmaf(a[i], bf[j], acc[i][j]);
        }
        __syncthreads();
    }

    // Epilogue: (acc + bias)*SCALE + pos[ts[t], h]
    const float bv = bias[d];
    #pragma unroll
    for (int i = 0; i < 8; i++) {
        const int tloc = ty * 8 + i;
        const int t = t0 + tloc;
        const int p = tsS[tloc];
        const float4 pv = *(const float4*)(pos + (long)p * Hh + h0 + tx * 4);
        float4 o;
        o.x = (acc[i][0] + bv) * SCALE_F + pv.x;
        o.y = (acc[i][1] + bv) * SCALE_F + pv.y;
        o.z = (acc[i][2] + bv) * SCALE_F + pv.z;
        o.w = (acc[i][3] + bv) * SCALE_F + pv.w;
        *(float4*)(out + ((long)b * Tt + t) * Hh + h0 + tx * 4) = o;
    }
}

extern "C" void kernel_launch(void* const* d_in, const int* in_sizes, int n_in,
                              void* d_out, int out_size) {
    const float* features = (const float*)d_in[0];   // B*T*C
    const int*   ts       = (const int*)d_in[1];     // B*T
    const int*   date_idx = (const int*)d_in[2];     // B
    const float* W        = (const float*)d_in[3];   // N_DATES*H*C
    const float* bias     = (const float*)d_in[4];   // N_DATES
    const float* pos      = (const float*)d_in[5];   // MAX_F*H
    float* out = (float*)d_out;

    dim3 grid(Hh / BN, Tt / BM, Bb);   // 16 x 8 x 32
    dim3 block(256);
    embed_kernel<<<grid, block>>>(features, ts, date_idx, W, bias, pos, out);
}

// round 3
// speedup vs baseline: 2.7889x; 2.7889x over previous
#include <cuda_runtime.h>
#include <cuda_bf16.h>
#include <cstdint>

// out[b,t,h] = (sum_c W[d[b],h,c]*f[b,t,c] + bias[d])*32 + pos[ts[b,t],h]
// B=32,T=1024,C=512,H=1024. bf16 split-3 GEMM on mma.sync (HMMA), cp.async pipeline.

#define Bb 32
#define Tt 1024
#define Cc 512
#define Hh 1024
#define SCALE_F 32.0f

#define BM 128
#define BN 128
#define BK 64                 // bf16 k per chunk
#define NCH (Cc/BK)           // 8
#define STAGE_BYTES 65536     // Ahi 16K + Alo 16K + Bhi 16K + Blo 16K
#define NSTAGE 3

// Pre-split scratch (bf16 hi/lo of features and per-b gathered W)
__device__ __align__(16) __nv_bfloat16 g_fhi[(size_t)Bb*Tt*Cc];
__device__ __align__(16) __nv_bfloat16 g_flo[(size_t)Bb*Tt*Cc];
__device__ __align__(16) __nv_bfloat16 g_whi[(size_t)Bb*Hh*Cc];
__device__ __align__(16) __nv_bfloat16 g_wlo[(size_t)Bb*Hh*Cc];

__device__ __forceinline__ uint32_t s2u(const void* p) {
    uint32_t a;
    asm("{ .reg .u64 t; cvta.to.shared.u64 t, %1; cvt.u32.u64 %0, t; }" : "=r"(a) : "l"(p));
    return a;
}

__device__ __forceinline__ uint32_t lds32(uint32_t a) {
    uint32_t v;
    asm volatile("ld.shared.b32 %0, [%1];" : "=r"(v) : "r"(a));
    return v;
}

__device__ __forceinline__ void mma16816(float* d, const uint32_t* a, const uint32_t* b) {
    asm volatile(
        "mma.sync.aligned.m16n8k16.row.col.f32.bf16.bf16.f32 "
        "{%0,%1,%2,%3}, {%4,%5,%6,%7}, {%8,%9}, {%0,%1,%2,%3};"
        : "+f"(d[0]), "+f"(d[1]), "+f"(d[2]), "+f"(d[3])
        : "r"(a[0]), "r"(a[1]), "r"(a[2]), "r"(a[3]), "r"(b[0]), "r"(b[1]));
}

// split 2 fp32 -> packed bf16x2 hi and lo
__device__ __forceinline__ void split2(float x, float y, uint32_t& hi, uint32_t& lo) {
    __nv_bfloat16 hx = __float2bfloat16(x);
    __nv_bfloat16 hy = __float2bfloat16(y);
    __nv_bfloat16 lx = __float2bfloat16(x - __bfloat162float(hx));
    __nv_bfloat16 ly = __float2bfloat16(y - __bfloat162float(hy));
    __nv_bfloat162 h; h.x = hx; h.y = hy;
    __nv_bfloat162 l; l.x = lx; l.y = ly;
    hi = *(uint32_t*)&h;
    lo = *(uint32_t*)&l;
}

// Pre-pass 1: features fp32 -> hi/lo bf16
__global__ __launch_bounds__(256) void prep_f(const float4* __restrict__ f) {
    size_t i = (size_t)blockIdx.x * 256 + threadIdx.x;   // over B*T*C/4
    float4 v = f[i];
    uint2 hi, lo;
    split2(v.x, v.y, hi.x, lo.x);
    split2(v.z, v.w, hi.y, lo.y);
    ((uint2*)g_fhi)[i] = hi;
    ((uint2*)g_flo)[i] = lo;
}

// Pre-pass 2: gather W[date_idx[b]] -> per-b hi/lo bf16
__global__ __launch_bounds__(256) void prep_w(const float4* __restrict__ W,
                                              const int* __restrict__ date_idx) {
    int b = blockIdx.y;
    int d = date_idx[b];
    size_t i = (size_t)blockIdx.x * 256 + threadIdx.x;   // over H*C/4 = 131072
    float4 v = W[(size_t)d * (Hh * Cc / 4) + i];
    uint2 hi, lo;
    split2(v.x, v.y, hi.x, lo.x);
    split2(v.z, v.w, hi.y, lo.y);
    ((uint2*)g_whi)[(size_t)b * (Hh * Cc / 4) + i] = hi;
    ((uint2*)g_wlo)[(size_t)b * (Hh * Cc / 4) + i] = lo;
}

// Main fused GEMM. smem stage: [Ahi 16K][Alo 16K][Bhi 16K][Blo 16K]
// word layout per tile: word(row,kw) at row*128 + ((kw ^ 4*(row&7))<<2), kw=0..31.
__global__ __launch_bounds__(512) void gemm_main(const int* __restrict__ ts,
                                                 const int* __restrict__ date_idx,
                                                 const float* __restrict__ bias,
                                                 const float* __restrict__ pos,
                                                 float* __restrict__ out) {
    extern __shared__ char smem[];
    const uint32_t sb = s2u(smem);
    const int tid = threadIdx.x;
    const int b = blockIdx.z, t0 = blockIdx.y * BM, h0 = blockIdx.x * BN;

    const __nv_bfloat16* fhiB = g_fhi + ((size_t)b * Tt + t0) * Cc;
    const __nv_bfloat16* floB = g_flo + ((size_t)b * Tt + t0) * Cc;
    const __nv_bfloat16* whiB = g_whi + ((size_t)b * Hh + h0) * Cc;
    const __nv_bfloat16* wloB = g_wlo + ((size_t)b * Hh + h0) * Cc;

    // cp.async one chunk (64 bf16 of K) into a stage: 4096 x 16B, 8 per thread
    auto issue = [&](int stage, int chunk) {
        const int k0 = chunk * BK;
        const uint32_t stb = sb + stage * STAGE_BYTES;
        #pragma unroll
        for (int it = 0; it < 8; it++) {
            const int buf = it >> 1;                        // 0:Ahi 1:Alo 2:Bhi 3:Blo
            const int s_ = (tid + (it & 1) * 512);          // 0..1023
            const int row = s_ >> 3, j = s_ & 7;
            const __nv_bfloat16* src;
            if (buf == 0)      src = fhiB + (size_t)row * Cc + k0 + j * 8;
            else if (buf == 1) src = floB + (size_t)row * Cc + k0 + j * 8;
            else if (buf == 2) src = whiB + (size_t)row * Cc + k0 + j * 8;
            else               src = wloB + (size_t)row * Cc + k0 + j * 8;
            uint32_t dst = stb + buf * 16384 + row * 128 + (((4 * j) ^ (4 * (row & 7))) << 2);
            asm volatile("cp.async.cg.shared.global [%0], [%1], 16;" :: "r"(dst), "l"(src));
        }
        asm volatile("cp.async.commit_group;");
    };

    const int w = tid >> 5, lane = tid & 31;
    const int wm = w >> 2, wn = w & 3;                      // 4x4 warps
    const int m0 = wm * 32, n0 = wn * 32;                   // warp tile 32x32
    const int g = lane >> 2, c4 = lane & 3;
    const uint32_t sw = 4 * g;

    float acc[2][4][4] = {};

    issue(0, 0);
    issue(1, 1);

    #pragma unroll 1
    for (int i = 0; i < NCH; i++) {
        if (i < NCH - 2) asm volatile("cp.async.wait_group 1;");
        else             asm volatile("cp.async.wait_group 0;");
        __syncthreads();
        if (i + 2 < NCH) issue((i + 2) % NSTAGE, i + 2);

        const uint32_t abase = sb + (i % NSTAGE) * STAGE_BYTES;
        #pragma unroll
        for (int ks = 0; ks < 4; ks++) {
            const uint32_t kc0 = ((8 * ks + c4) ^ sw) << 2;
            const uint32_t kc1 = ((8 * ks + 4 + c4) ^ sw) << 2;
            uint32_t ah[2][4], al[2][4], bh[4][2], bl[4][2];
            #pragma unroll
            for (int im = 0; im < 2; im++) {
                const uint32_t r0 = abase + (m0 + 16 * im + g) * 128;
                ah[im][0] = lds32(r0 + kc0);
                ah[im][1] = lds32(r0 + 1024 + kc0);
                ah[im][2] = lds32(r0 + kc1);
                ah[im][3] = lds32(r0 + 1024 + kc1);
                al[im][0] = lds32(r0 + 16384 + kc0);
                al[im][1] = lds32(r0 + 17408 + kc0);
                al[im][2] = lds32(r0 + 16384 + kc1);
                al[im][3] = lds32(r0 + 17408 + kc1);
            }
            #pragma unroll
            for (int jn = 0; jn < 4; jn++) {
                const uint32_t rb = abase + 32768 + (n0 + 8 * jn + g) * 128;
                bh[jn][0] = lds32(rb + kc0);
                bh[jn][1] = lds32(rb + kc1);
                bl[jn][0] = lds32(rb + 16384 + kc0);
                bl[jn][1] = lds32(rb + 16384 + kc1);
            }
            #pragma unroll
            for (int im = 0; im < 2; im++)
                #pragma unroll
                for (int jn = 0; jn < 4; jn++) {
                    mma16816(acc[im][jn], ah[im], bh[jn]);   // hi*hi
                    mma16816(acc[im][jn], ah[im], bl[jn]);   // hi*lo
                    mma16816(acc[im][jn], al[im], bh[jn]);   // lo*hi
                }
        }
        __syncthreads();
    }

    // Epilogue: (acc + bias)*32 + pos[ts[t], h]
    const int d = date_idx[b];
    const float bv = bias[d];
    #pragma unroll
    for (int im = 0; im < 2; im++) {
        const int r0 = m0 + 16 * im + g;
        const int tA = t0 + r0, tB = t0 + r0 + 8;
        const int pA = ts[b * Tt + tA];
        const int pB = ts[b * Tt + tB];
        const float* posA = pos + (size_t)pA * Hh;
        const float* posB = pos + (size_t)pB * Hh;
        float* outA = out + ((size_t)b * Tt + tA) * Hh;
        float* outB = out + ((size_t)b * Tt + tB) * Hh;
        #pragma unroll
        for (int jn = 0; jn < 4; jn++) {
            const int col = h0 + n0 + 8 * jn + 2 * c4;
            float2 pv = *(const float2*)(posA + col);
            float2 o;
            o.x = (acc[im][jn][0] + bv) * SCALE_F + pv.x;
            o.y = (acc[im][jn][1] + bv) * SCALE_F + pv.y;
            *(float2*)(outA + col) = o;
            pv = *(const float2*)(posB + col);
            o.x = (acc[im][jn][2] + bv) * SCALE_F + pv.x;
            o.y = (acc[im][jn][3] + bv) * SCALE_F + pv.y;
            *(float2*)(outB + col) = o;
        }
    }
}

extern "C" void kernel_launch(void* const* d_in, const int* in_sizes, int n_in,
                              void* d_out, int out_size) {
    const float* features = (const float*)d_in[0];
    const int*   ts       = (const int*)d_in[1];
    const int*   date_idx = (const int*)d_in[2];
    const float* W        = (const float*)d_in[3];
    const float* bias     = (const float*)d_in[4];
    const float* pos      = (const float*)d_in[5];
    float* out = (float*)d_out;

    cudaFuncSetAttribute(gemm_main, cudaFuncAttributeMaxDynamicSharedMemorySize,
                         NSTAGE * STAGE_BYTES);

    prep_f<<<(Bb * Tt * Cc / 4) / 256, 256>>>((const float4*)features);
    prep_w<<<dim3(Hh * Cc / 4 / 256, Bb), 256>>>((const float4*)W, date_idx);
    gemm_main<<<dim3(Hh / BN, Tt / BM, Bb), 512, NSTAGE * STAGE_BYTES>>>(
        ts, date_idx, bias, pos, out);
}

// round 4
// speedup vs baseline: 5.7584x; 2.0648x over previous
#include <cuda_runtime.h>
#include <cuda_fp16.h>
#include <cstdint>

// out[b,t,h] = (sum_c W[d[b],h,c]*f[b,t,c] + bias[d])*32 + pos[ts[b,t],h]
// B=32,T=1024,C=512,H=1024. Single-pass fp16 mma.sync GEMM, fp32 accum.

#define Bb 32
#define Tt 1024
#define Cc 512
#define Hh 1024
#define SCALE_F 32.0f

#define BM 128
#define BN 128
#define BK 64                 // fp16 k per chunk (128B rows)
#define NCH (Cc/BK)           // 8
#define STAGE_BYTES 32768     // A 16K + B 16K
#define NSTAGE 3

// fp16 scratch: features and per-b gathered W
__device__ __align__(16) __half g_fh[(size_t)Bb*Tt*Cc];
__device__ __align__(16) __half g_wh[(size_t)Bb*Hh*Cc];

__device__ __forceinline__ uint32_t s2u(const void* p) {
    uint32_t a;
    asm("{ .reg .u64 t; cvta.to.shared.u64 t, %1; cvt.u32.u64 %0, t; }" : "=r"(a) : "l"(p));
    return a;
}

__device__ __forceinline__ void ldmx4(uint32_t* r, uint32_t addr) {
    asm volatile("ldmatrix.sync.aligned.m8n8.x4.shared.b16 {%0,%1,%2,%3}, [%4];"
                 : "=r"(r[0]), "=r"(r[1]), "=r"(r[2]), "=r"(r[3]) : "r"(addr));
}

__device__ __forceinline__ void mma16816(float* d, const uint32_t* a, const uint32_t* b) {
    asm volatile(
        "mma.sync.aligned.m16n8k16.row.col.f32.f16.f16.f32 "
        "{%0,%1,%2,%3}, {%4,%5,%6,%7}, {%8,%9}, {%0,%1,%2,%3};"
        : "+f"(d[0]), "+f"(d[1]), "+f"(d[2]), "+f"(d[3])
        : "r"(a[0]), "r"(a[1]), "r"(a[2]), "r"(a[3]), "r"(b[0]), "r"(b[1]));
}

// Pre-pass 1: features fp32 -> fp16
__global__ __launch_bounds__(256) void prep_f(const float4* __restrict__ f) {
    size_t i = (size_t)blockIdx.x * 256 + threadIdx.x;   // over B*T*C/4
    float4 v = f[i];
    __half2 h0 = __floats2half2_rn(v.x, v.y);
    __half2 h1 = __floats2half2_rn(v.z, v.w);
    uint2 o; o.x = *(uint32_t*)&h0; o.y = *(uint32_t*)&h1;
    ((uint2*)g_fh)[i] = o;
}

// Pre-pass 2: gather W[date_idx[b]] -> fp16
__global__ __launch_bounds__(256) void prep_w(const float4* __restrict__ W,
                                              const int* __restrict__ date_idx) {
    int b = blockIdx.y;
    int d = date_idx[b];
    size_t i = (size_t)blockIdx.x * 256 + threadIdx.x;   // over H*C/4
    float4 v = W[(size_t)d * (Hh * Cc / 4) + i];
    __half2 h0 = __floats2half2_rn(v.x, v.y);
    __half2 h1 = __floats2half2_rn(v.z, v.w);
    uint2 o; o.x = *(uint32_t*)&h0; o.y = *(uint32_t*)&h1;
    ((uint2*)g_wh)[(size_t)b * (Hh * Cc / 4) + i] = o;
}

// Main GEMM. Stage layout: [A 128x128B][B 128x128B], word kw of row r at
// byte r*128 + ((kw ^ 4*(r&7))<<2).
__global__ __launch_bounds__(512, 2) void gemm_main(const int* __restrict__ ts,
                                                    const int* __restrict__ date_idx,
                                                    const float* __restrict__ bias,
                                                    const float* __restrict__ pos,
                                                    float* __restrict__ out) {
    extern __shared__ char smem[];
    const uint32_t sb = s2u(smem);
    const int tid = threadIdx.x;
    const int b = blockIdx.z, t0 = blockIdx.y * BM, h0 = blockIdx.x * BN;

    const __half* fhB = g_fh + ((size_t)b * Tt + t0) * Cc;
    const __half* whB = g_wh + ((size_t)b * Hh + h0) * Cc;

    // cp.async one chunk (64 fp16 of K): 2048 x 16B, 4 per thread
    auto issue = [&](int stage, int chunk) {
        const int k0 = chunk * BK;
        const uint32_t stb = sb + stage * STAGE_BYTES;
        #pragma unroll
        for (int it = 0; it < 4; it++) {
            const int idx = tid + it * 512;               // 0..2047
            const int buf = idx >> 10;                    // 0:A 1:B
            const int r = (idx >> 3) & 127, j = idx & 7;
            const __half* src = (buf ? whB : fhB) + (size_t)r * Cc + k0 + j * 8;
            uint32_t dst = stb + buf * 16384 + r * 128 + (((4 * j) ^ (4 * (r & 7))) << 2);
            asm volatile("cp.async.cg.shared.global [%0], [%1], 16;" :: "r"(dst), "l"(src));
        }
        asm volatile("cp.async.commit_group;");
    };

    const int w = tid >> 5, l = tid & 31;
    const int wm = w >> 2, wn = w & 3;                    // 4x4 warps
    const int m0 = wm * 32, n0 = wn * 32;                 // warp tile 32x32
    const int g = l >> 2, c4 = l & 3;

    // ldmatrix lane address components
    const uint32_t swl = 4 * (l & 7);
    const uint32_t aRow = (uint32_t)(m0 + (l & 15)) * 128;       // + 2048*im
    const uint32_t aKsel = (l >> 4) * 4;
    const uint32_t bRow0 = (uint32_t)(n0 + ((l >> 4) * 8) + (l & 7)) * 128;  // + 2048*jp
    const uint32_t bKsel = ((l >> 3) & 1) * 4;

    float acc[2][4][4] = {};

    issue(0, 0);
    issue(1, 1);

    #pragma unroll 1
    for (int i = 0; i < NCH; i++) {
        if (i < NCH - 1) asm volatile("cp.async.wait_group 1;");
        else             asm volatile("cp.async.wait_group 0;");
        __syncthreads();
        if (i + 2 < NCH) issue((i + 2) % NSTAGE, i + 2);

        const uint32_t stA = sb + (i % NSTAGE) * STAGE_BYTES;
        const uint32_t stB = stA + 16384;
        #pragma unroll
        for (int ks = 0; ks < 4; ks++) {
            uint32_t a[2][4], bf[4][2];
            const uint32_t ak = ((8 * ks + aKsel) ^ swl) << 2;
            const uint32_t bk = ((8 * ks + bKsel) ^ swl) << 2;
            #pragma unroll
            for (int im = 0; im < 2; im++)
                ldmx4(a[im], stA + aRow + im * 2048 + ak);
            #pragma unroll
            for (int jp = 0; jp < 2; jp++) {
                uint32_t r[4];
                ldmx4(r, stB + bRow0 + jp * 2048 + bk);
                bf[2 * jp][0] = r[0]; bf[2 * jp][1] = r[1];
                bf[2 * jp + 1][0] = r[2]; bf[2 * jp + 1][1] = r[3];
            }
            #pragma unroll
            for (int im = 0; im < 2; im++)
                #pragma unroll
                for (int jn = 0; jn < 4; jn++)
                    mma16816(acc[im][jn], a[im], bf[jn]);
        }
    }

    // Epilogue: (acc + bias)*32 + pos[ts[t], h]
    const int d = date_idx[b];
    const float bv = bias[d];
    #pragma unroll
    for (int im = 0; im < 2; im++) {
        const int r0 = m0 + 16 * im + g;
        const int tA = t0 + r0, tB = t0 + r0 + 8;
        const int pA = ts[b * Tt + tA];
        const int pB = ts[b * Tt + tB];
        const float* posA = pos + (size_t)pA * Hh;
        const float* posB = pos + (size_t)pB * Hh;
        float* outA = out + ((size_t)b * Tt + tA) * Hh;
        float* outB = out + ((size_t)b * Tt + tB) * Hh;
        #pragma unroll
        for (int jn = 0; jn < 4; jn++) {
            const int col = h0 + n0 + 8 * jn + 2 * c4;
            float2 pv = *(const float2*)(posA + col);
            float2 o;
            o.x = (acc[im][jn][0] + bv) * SCALE_F + pv.x;
            o.y = (acc[im][jn][1] + bv) * SCALE_F + pv.y;
            *(float2*)(outA + col) = o;
            pv = *(const float2*)(posB + col);
            o.x = (acc[im][jn][2] + bv) * SCALE_F + pv.x;
            o.y = (acc[im][jn][3] + bv) * SCALE_F + pv.y;
            *(float2*)(outB + col) = o;
        }
    }
}

extern "C" void kernel_launch(void* const* d_in, const int* in_sizes, int n_in,
                              void* d_out, int out_size) {
    const float* features = (const float*)d_in[0];
    const int*   ts       = (const int*)d_in[1];
    const int*   date_idx = (const int*)d_in[2];
    const float* W        = (const float*)d_in[3];
    const float* bias     = (const float*)d_in[4];
    const float* pos      = (const float*)d_in[5];
    float* out = (float*)d_out;

    cudaFuncSetAttribute(gemm_main, cudaFuncAttributeMaxDynamicSharedMemorySize,
                         NSTAGE * STAGE_BYTES);

    prep_f<<<(Bb * Tt * Cc / 4) / 256, 256>>>((const float4*)features);
    prep_w<<<dim3(Hh * Cc / 4 / 256, Bb), 256>>>((const float4*)W, date_idx);
    gemm_main<<<dim3(Hh / BN, Tt / BM, Bb), 512, NSTAGE * STAGE_BYTES>>>(
        ts, date_idx, bias, pos, out);
}

// round 5
// speedup vs baseline: 6.1950x; 1.0758x over previous
#include <cuda_runtime.h>
#include <cuda_fp16.h>
#include <cstdint>

// out[b,t,h] = (sum_c W[d[b],h,c]*f[b,t,c] + bias[d])*32 + pos[ts[b,t],h]
// B=32,T=1024,C=512,H=1024. fp16 mma.sync GEMM (fp32 accum), cp.async 3-stage,
// warp tile 64x32, merged fp32->fp16 prep pass.

#define Bb 32
#define Tt 1024
#define Cc 512
#define Hh 1024
#define SCALE_F 32.0f

#define BM 128
#define BN 128
#define BK 64                 // fp16 k per chunk (128B rows)
#define NCH (Cc/BK)           // 8
#define STAGE_BYTES 32768     // A 16K + B 16K
#define NSTAGE 3

#define NF4 4194304           // B*T*C/4   (2^22)
#define HC4 131072            // H*C/4     (2^17)

// fp16 scratch: features and per-b gathered W
__device__ __align__(16) __half g_fh[(size_t)Bb*Tt*Cc];
__device__ __align__(16) __half g_wh[(size_t)Bb*Hh*Cc];

__device__ __forceinline__ uint32_t s2u(const void* p) {
    uint32_t a;
    asm("{ .reg .u64 t; cvta.to.shared.u64 t, %1; cvt.u32.u64 %0, t; }" : "=r"(a) : "l"(p));
    return a;
}

__device__ __forceinline__ void ldmx4(uint32_t* r, uint32_t addr) {
    asm volatile("ldmatrix.sync.aligned.m8n8.x4.shared.b16 {%0,%1,%2,%3}, [%4];"
                 : "=r"(r[0]), "=r"(r[1]), "=r"(r[2]), "=r"(r[3]) : "r"(addr));
}

__device__ __forceinline__ void mma16816(float* d, const uint32_t* a, const uint32_t* b) {
    asm volatile(
        "mma.sync.aligned.m16n8k16.row.col.f32.f16.f16.f32 "
        "{%0,%1,%2,%3}, {%4,%5,%6,%7}, {%8,%9}, {%0,%1,%2,%3};"
        : "+f"(d[0]), "+f"(d[1]), "+f"(d[2]), "+f"(d[3])
        : "r"(a[0]), "r"(a[1]), "r"(a[2]), "r"(a[3]), "r"(b[0]), "r"(b[1]));
}

// Merged prep: convert features (first NF4 float4s) and gathered W (next NF4).
__global__ __launch_bounds__(256) void prep_all(const float4* __restrict__ f,
                                                const float4* __restrict__ W,
                                                const int* __restrict__ date_idx) {
    size_t i = (size_t)blockIdx.x * 256 + threadIdx.x;   // 0 .. 2*NF4-1
    float4 v;
    uint2* dst;
    if (i < NF4) {
        v = f[i];
        dst = (uint2*)g_fh + i;
    } else {
        size_t j = i - NF4;
        int b = (int)(j >> 17);                          // j / HC4
        size_t i2 = j & (HC4 - 1);
        int d = date_idx[b];
        v = W[(size_t)d * HC4 + i2];
        dst = (uint2*)g_wh + j;
    }
    __half2 h0 = __floats2half2_rn(v.x, v.y);
    __half2 h1 = __floats2half2_rn(v.z, v.w);
    uint2 o; o.x = *(uint32_t*)&h0; o.y = *(uint32_t*)&h1;
    *dst = o;
}

// Main GEMM. Stage layout: [A 128x128B][B 128x128B], word kw of row r at
// byte r*128 + ((kw ^ 4*(r&7))<<2).
__global__ __launch_bounds__(256, 2) void gemm_main(const int* __restrict__ ts,
                                                    const int* __restrict__ date_idx,
                                                    const float* __restrict__ bias,
                                                    const float* __restrict__ pos,
                                                    float* __restrict__ out) {
    extern __shared__ char smem[];
    const uint32_t sb = s2u(smem);
    const int tid = threadIdx.x;
    const int b = blockIdx.z, t0 = blockIdx.y * BM, h0 = blockIdx.x * BN;

    const __half* fhB = g_fh + ((size_t)b * Tt + t0) * Cc;
    const __half* whB = g_wh + ((size_t)b * Hh + h0) * Cc;

    // cp.async one chunk (64 fp16 of K): 2048 x 16B, 8 per thread
    auto issue = [&](int stage, int chunk) {
        const int k0 = chunk * BK;
        const uint32_t stb = sb + stage * STAGE_BYTES;
        #pragma unroll
        for (int it = 0; it < 8; it++) {
            const int idx = tid + it * 256;               // 0..2047
            const int buf = idx >> 10;                    // 0:A 1:B
            const int r = (idx >> 3) & 127, j = idx & 7;
            const __half* src = (buf ? whB : fhB) + (size_t)r * Cc + k0 + j * 8;
            uint32_t dst = stb + buf * 16384 + r * 128 + (((4 * j) ^ (4 * (r & 7))) << 2);
            asm volatile("cp.async.cg.shared.global [%0], [%1], 16;" :: "r"(dst), "l"(src));
        }
        asm volatile("cp.async.commit_group;");
    };

    const int w = tid >> 5, l = tid & 31;
    const int wm = w >> 2, wn = w & 3;                    // 2x4 warps
    const int m0 = wm * 64, n0 = wn * 32;                 // warp tile 64x32
    const int g = l >> 2, c4 = l & 3;

    // ldmatrix lane address components
    const uint32_t swl = 4 * (l & 7);
    const uint32_t aRow = (uint32_t)(m0 + (l & 15)) * 128;       // + 2048*im
    const uint32_t aKsel = (l >> 4) * 4;
    const uint32_t bRow0 = (uint32_t)(n0 + ((l >> 4) * 8) + (l & 7)) * 128;  // + 2048*jp
    const uint32_t bKsel = ((l >> 3) & 1) * 4;

    float acc[4][4][4] = {};

    issue(0, 0);
    issue(1, 1);

    #pragma unroll 1
    for (int i = 0; i < NCH; i++) {
        if (i < NCH - 1) asm volatile("cp.async.wait_group 1;");
        else             asm volatile("cp.async.wait_group 0;");
        __syncthreads();
        if (i + 2 < NCH) issue((i + 2) % NSTAGE, i + 2);

        const uint32_t stA = sb + (i % NSTAGE) * STAGE_BYTES;
        const uint32_t stB = stA + 16384;
        #pragma unroll
        for (int ks = 0; ks < 4; ks++) {
            uint32_t a[4][4], bf[4][2];
            const uint32_t ak = ((8 * ks + aKsel) ^ swl) << 2;
            const uint32_t bk = ((8 * ks + bKsel) ^ swl) << 2;
            #pragma unroll
            for (int im = 0; im < 4; im++)
                ldmx4(a[im], stA + aRow + im * 2048 + ak);
            #pragma unroll
            for (int jp = 0; jp < 2; jp++) {
                uint32_t r[4];
                ldmx4(r, stB + bRow0 + jp * 2048 + bk);
                bf[2 * jp][0] = r[0]; bf[2 * jp][1] = r[1];
                bf[2 * jp + 1][0] = r[2]; bf[2 * jp + 1][1] = r[3];
            }
            #pragma unroll
            for (int im = 0; im < 4; im++)
                #pragma unroll
                for (int jn = 0; jn < 4; jn++)
                    mma16816(acc[im][jn], a[im], bf[jn]);
        }
    }

    // Epilogue: (acc + bias)*32 + pos[ts[t], h]
    const int d = date_idx[b];
    const float bv = bias[d];
    #pragma unroll
    for (int im = 0; im < 4; im++) {
        const int r0 = m0 + 16 * im + g;
        const int tA = t0 + r0, tB = t0 + r0 + 8;
        const int pA = ts[b * Tt + tA];
        const int pB = ts[b * Tt + tB];
        const float* posA = pos + (size_t)pA * Hh;
        const float* posB = pos + (size_t)pB * Hh;
        float* outA = out + ((size_t)b * Tt + tA) * Hh;
        float* outB = out + ((size_t)b * Tt + tB) * Hh;
        #pragma unroll
        for (int jn = 0; jn < 4; jn++) {
            const int col = h0 + n0 + 8 * jn + 2 * c4;
            float2 pv = *(const float2*)(posA + col);
            float2 o;
            o.x = (acc[im][jn][0] + bv) * SCALE_F + pv.x;
            o.y = (acc[im][jn][1] + bv) * SCALE_F + pv.y;
            *(float2*)(outA + col) = o;
            pv = *(const float2*)(posB + col);
            o.x = (acc[im][jn][2] + bv) * SCALE_F + pv.x;
            o.y = (acc[im][jn][3] + bv) * SCALE_F + pv.y;
            *(float2*)(outB + col) = o;
        }
    }
}

extern "C" void kernel_launch(void* const* d_in, const int* in_sizes, int n_in,
                              void* d_out, int out_size) {
    const float* features = (const float*)d_in[0];
    const int*   ts       = (const int*)d_in[1];
    const int*   date_idx = (const int*)d_in[2];
    const float* W        = (const float*)d_in[3];
    const float* bias     = (const float*)d_in[4];
    const float* pos      = (const float*)d_in[5];
    float* out = (float*)d_out;

    cudaFuncSetAttribute(gemm_main, cudaFuncAttributeMaxDynamicSharedMemorySize,
                         NSTAGE * STAGE_BYTES);

    prep_all<<<(2 * NF4) / 256, 256>>>((const float4*)features, (const float4*)W, date_idx);
    gemm_main<<<dim3(Hh / BN, Tt / BM, Bb), 256, NSTAGE * STAGE_BYTES>>>(
        ts, date_idx, bias, pos, out);
}

// round 6
// speedup vs baseline: 6.5052x; 1.0501x over previous
#include <cuda_runtime.h>
#include <cuda_fp16.h>
#include <cstdint>

// out[b,t,h] = (sum_c W[d[b],h,c]*f[b,t,c] + bias[d])*32 + pos[ts[b,t],h]
// B=32,T=1024,C=512,H=1024. fp16 mma.sync GEMM (fp32 accum).
// Stage loads via cp.async.bulk (TMA) from pre-swizzled chunk-major scratch.

#define Bb 32
#define Tt 1024
#define Cc 512
#define Hh 1024
#define SCALE_F 32.0f

#define BM 128
#define BN 128
#define BK 64                 // fp16 k per chunk (128B rows)
#define NCH (Cc/BK)           // 8
#define STAGE_BYTES 32768     // A 16K + B 16K
#define NSTAGE 3
#define SM_MBAR (NSTAGE * STAGE_BYTES)      // 98304
#define SM_TOTAL (SM_MBAR + 64)

#define NF4 4194304           // B*T*C/4   (2^22)
#define HC4 131072            // H*C/4     (2^17)

// Pre-swizzled chunk-major fp16 scratch: [b][chunk][row][128B]
__device__ __align__(128) __half g_fh[(size_t)Bb*Tt*Cc];
__device__ __align__(128) __half g_wh[(size_t)Bb*Hh*Cc];

__device__ __forceinline__ uint32_t s2u(const void* p) {
    uint32_t a;
    asm("{ .reg .u64 t; cvta.to.shared.u64 t, %1; cvt.u32.u64 %0, t; }" : "=r"(a) : "l"(p));
    return a;
}

__device__ __forceinline__ void ldmx4(uint32_t* r, uint32_t addr) {
    asm volatile("ldmatrix.sync.aligned.m8n8.x4.shared.b16 {%0,%1,%2,%3}, [%4];"
                 : "=r"(r[0]), "=r"(r[1]), "=r"(r[2]), "=r"(r[3]) : "r"(addr));
}

__device__ __forceinline__ void mma16816(float* d, const uint32_t* a, const uint32_t* b) {
    asm volatile(
        "mma.sync.aligned.m16n8k16.row.col.f32.f16.f16.f32 "
        "{%0,%1,%2,%3}, {%4,%5,%6,%7}, {%8,%9}, {%0,%1,%2,%3};"
        : "+f"(d[0]), "+f"(d[1]), "+f"(d[2]), "+f"(d[3])
        : "r"(a[0]), "r"(a[1]), "r"(a[2]), "r"(a[3]), "r"(b[0]), "r"(b[1]));
}

// Prep: fp32 -> fp16, gathered (W), rewritten chunk-major pre-swizzled.
// Element (b, row, j[0..127] float4-index):
//   chunk=j>>4, unit jp=(j>>1)&7, half=j&1
//   dst byte = (((b*8+chunk)*1024 + row)<<7) + ((jp ^ (row&7))<<4) + half*8
__global__ __launch_bounds__(256) void prep_all(const float4* __restrict__ f,
                                                const float4* __restrict__ W,
                                                const int* __restrict__ date_idx) {
    size_t idx = (size_t)blockIdx.x * 256 + threadIdx.x;   // 0 .. 2*NF4-1
    float4 v;
    char* base;
    int b, row, j;
    if (idx < NF4) {
        b = (int)(idx >> 17);
        int rem = (int)(idx & 131071);
        row = rem >> 7; j = rem & 127;
        v = f[idx];
        base = (char*)g_fh;
    } else {
        size_t k = idx - NF4;
        b = (int)(k >> 17);
        int rem = (int)(k & 131071);
        row = rem >> 7; j = rem & 127;
        int d = date_idx[b];
        v = W[(size_t)d * HC4 + (size_t)rem];
        base = (char*)g_wh;
    }
    __half2 h0 = __floats2half2_rn(v.x, v.y);
    __half2 h1 = __floats2half2_rn(v.z, v.w);
    uint2 o; o.x = *(uint32_t*)&h0; o.y = *(uint32_t*)&h1;
    int chunk = j >> 4, jp = (j >> 1) & 7, half = j & 1;
    size_t off = ((((size_t)(b * 8 + chunk)) * 1024 + row) << 7)
               + ((uint32_t)(jp ^ (row & 7)) << 4) + half * 8;
    *(uint2*)(base + off) = o;
}

// Main GEMM. In-stage layout identical to R5: word kw of row r at
// byte r*128 + ((kw ^ 4*(r&7))<<2). Stage filled by one 16KB bulk copy each
// for A and B (source already swizzled).
__global__ __launch_bounds__(256, 2) void gemm_main(const int* __restrict__ ts,
                                                    const int* __restrict__ date_idx,
                                                    const float* __restrict__ bias,
                                                    const float* __restrict__ pos,
                                                    float* __restrict__ out) {
    extern __shared__ char smem[];
    const uint32_t sb = s2u(smem);
    const int tid = threadIdx.x;
    const int b = blockIdx.z, t0 = blockIdx.y * BM, h0 = blockIdx.x * BN;

    // chunk-major sources: [b][chunk][row][128B]
    const char* fbase = (const char*)g_fh + (((size_t)b * 8) * 1024 + t0) * 128;
    const char* wbase = (const char*)g_wh + (((size_t)b * 8) * 1024 + h0) * 128;

    if (tid == 0) {
        #pragma unroll
        for (int s = 0; s < NSTAGE; s++)
            asm volatile("mbarrier.init.shared.b64 [%0], 1;"
                         :: "r"(sb + SM_MBAR + s * 8) : "memory");
    }
    __syncthreads();

    auto issue = [&](int chunk) {
        const int slot = chunk % NSTAGE;
        const uint32_t mb = sb + SM_MBAR + slot * 8;
        const uint32_t stb = sb + slot * STAGE_BYTES;
        const uint64_t srcA = (uint64_t)(fbase + (size_t)chunk * (1024 * 128));
        const uint64_t srcB = (uint64_t)(wbase + (size_t)chunk * (1024 * 128));
        asm volatile("mbarrier.arrive.expect_tx.shared.b64 _, [%0], %1;"
                     :: "r"(mb), "r"((uint32_t)STAGE_BYTES) : "memory");
        asm volatile("cp.async.bulk.shared::cluster.global.mbarrier::complete_tx::bytes "
                     "[%0], [%1], %2, [%3];"
                     :: "r"(stb), "l"(srcA), "r"(16384u), "r"(mb) : "memory");
        asm volatile("cp.async.bulk.shared::cluster.global.mbarrier::complete_tx::bytes "
                     "[%0], [%1], %2, [%3];"
                     :: "r"(stb + 16384u), "l"(srcB), "r"(16384u), "r"(mb) : "memory");
    };

    if (tid == 0) { issue(0); issue(1); issue(2); }

    const int w = tid >> 5, l = tid & 31;
    const int wm = w >> 2, wn = w & 3;                    // 2x4 warps
    const int m0 = wm * 64, n0 = wn * 32;                 // warp tile 64x32
    const int g = l >> 2, c4 = l & 3;

    const uint32_t swl = 4 * (l & 7);
    const uint32_t aRow = (uint32_t)(m0 + (l & 15)) * 128;
    const uint32_t aKsel = (l >> 4) * 4;
    const uint32_t bRow0 = (uint32_t)(n0 + ((l >> 4) * 8) + (l & 7)) * 128;
    const uint32_t bKsel = ((l >> 3) & 1) * 4;

    float acc[4][4][4] = {};

    #pragma unroll 1
    for (int i = 0; i < NCH; i++) {
        // wait stage full (parity = (i/NSTAGE)&1)
        {
            const uint32_t mb = sb + SM_MBAR + (i % NSTAGE) * 8;
            const uint32_t par = (uint32_t)((i / NSTAGE) & 1);
            uint32_t done;
            asm volatile("{\n .reg .pred p;\n mbarrier.try_wait.parity.acquire.cta.shared::cta.b64 p, [%1], %2;\n selp.b32 %0,1,0,p;\n}"
                         : "=r"(done) : "r"(mb), "r"(par) : "memory");
            if (!done) {
                asm volatile("{\n .reg .pred P1;\nWL_%=:\n mbarrier.try_wait.parity.acquire.cta.shared::cta.b64 P1, [%0], %1, 0x989680;\n @P1 bra.uni WD_%=;\n bra.uni WL_%=;\nWD_%=:\n}"
                             :: "r"(mb), "r"(par) : "memory");
            }
        }

        const uint32_t stA = sb + (i % NSTAGE) * STAGE_BYTES;
        const uint32_t stB = stA + 16384;
        #pragma unroll
        for (int ks = 0; ks < 4; ks++) {
            uint32_t a[4][4], bf[4][2];
            const uint32_t ak = ((8 * ks + aKsel) ^ swl) << 2;
            const uint32_t bk = ((8 * ks + bKsel) ^ swl) << 2;
            #pragma unroll
            for (int im = 0; im < 4; im++)
                ldmx4(a[im], stA + aRow + im * 2048 + ak);
            #pragma unroll
            for (int jp = 0; jp < 2; jp++) {
                uint32_t r[4];
                ldmx4(r, stB + bRow0 + jp * 2048 + bk);
                bf[2 * jp][0] = r[0]; bf[2 * jp][1] = r[1];
                bf[2 * jp + 1][0] = r[2]; bf[2 * jp + 1][1] = r[3];
            }
            #pragma unroll
            for (int im = 0; im < 4; im++)
                #pragma unroll
                for (int jn = 0; jn < 4; jn++)
                    mma16816(acc[im][jn], a[im], bf[jn]);
        }

        __syncthreads();                         // all warps done reading slot
        if (i + NSTAGE < NCH && tid == 0) issue(i + NSTAGE);
    }

    // Epilogue: (acc + bias)*32 + pos[ts[t], h]
    const int d = date_idx[b];
    const float bv = bias[d];
    #pragma unroll
    for (int im = 0; im < 4; im++) {
        const int r0 = m0 + 16 * im + g;
        const int tA = t0 + r0, tB = t0 + r0 + 8;
        const int pA = ts[b * Tt + tA];
        const int pB = ts[b * Tt + tB];
        const float* posA = pos + (size_t)pA * Hh;
        const float* posB = pos + (size_t)pB * Hh;
        float* outA = out + ((size_t)b * Tt + tA) * Hh;
        float* outB = out + ((size_t)b * Tt + tB) * Hh;
        #pragma unroll
        for (int jn = 0; jn < 4; jn++) {
            const int col = h0 + n0 + 8 * jn + 2 * c4;
            float2 pv = *(const float2*)(posA + col);
            float2 o;
            o.x = (acc[im][jn][0] + bv) * SCALE_F + pv.x;
            o.y = (acc[im][jn][1] + bv) * SCALE_F + pv.y;
            *(float2*)(outA + col) = o;
            pv = *(const float2*)(posB + col);
            o.x = (acc[im][jn][2] + bv) * SCALE_F + pv.x;
            o.y = (acc[im][jn][3] + bv) * SCALE_F + pv.y;
            *(float2*)(outB + col) = o;
        }
    }
}

extern "C" void kernel_launch(void* const* d_in, const int* in_sizes, int n_in,
                              void* d_out, int out_size) {
    const float* features = (const float*)d_in[0];
    const int*   ts       = (const int*)d_in[1];
    const int*   date_idx = (const int*)d_in[2];
    const float* W        = (const float*)d_in[3];
    const float* bias     = (const float*)d_in[4];
    const float* pos      = (const float*)d_in[5];
    float* out = (float*)d_out;

    cudaFuncSetAttribute(gemm_main, cudaFuncAttributeMaxDynamicSharedMemorySize, SM_TOTAL);

    prep_all<<<(2 * NF4) / 256, 256>>>((const float4*)features, (const float4*)W, date_idx);
    gemm_main<<<dim3(Hh / BN, Tt / BM, Bb), 256, SM_TOTAL>>>(
        ts, date_idx, bias, pos, out);
}

// round 7
// speedup vs baseline: 6.7258x; 1.0339x over previous
#include <cuda_runtime.h>
#include <cuda_fp16.h>
#include <cstdint>

// out[b,t,h] = (sum_c W[d[b],h,c]*f[b,t,c] + bias[d])*32 + pos[ts[b,t],h]
// B=32,T=1024,C=512,H=1024. fp16 mma.sync GEMM (fp32 accum), TMA bulk loads
// from pre-swizzled chunk-major scratch, register-fragment double buffering.

#define Bb 32
#define Tt 1024
#define Cc 512
#define Hh 1024
#define SCALE_F 32.0f

#define BM 128
#define BN 128
#define BK 64                 // fp16 k per chunk (128B rows)
#define NCH (Cc/BK)           // 8
#define STAGE_BYTES 32768     // A 16K + B 16K
#define NSTAGE 3
#define SM_MBAR (NSTAGE * STAGE_BYTES)      // 98304
#define SM_TOTAL (SM_MBAR + 64)

#define NF4 4194304           // B*T*C/4   (2^22)
#define HC4 131072            // H*C/4     (2^17)

// Pre-swizzled chunk-major fp16 scratch: [b][chunk][row][128B]
__device__ __align__(128) __half g_fh[(size_t)Bb*Tt*Cc];
__device__ __align__(128) __half g_wh[(size_t)Bb*Hh*Cc];

__device__ __forceinline__ uint32_t s2u(const void* p) {
    uint32_t a;
    asm("{ .reg .u64 t; cvta.to.shared.u64 t, %1; cvt.u32.u64 %0, t; }" : "=r"(a) : "l"(p));
    return a;
}

__device__ __forceinline__ void ldmx4(uint32_t* r, uint32_t addr) {
    asm volatile("ldmatrix.sync.aligned.m8n8.x4.shared.b16 {%0,%1,%2,%3}, [%4];"
                 : "=r"(r[0]), "=r"(r[1]), "=r"(r[2]), "=r"(r[3]) : "r"(addr));
}

__device__ __forceinline__ void mma16816(float* d, const uint32_t* a, const uint32_t* b) {
    asm volatile(
        "mma.sync.aligned.m16n8k16.row.col.f32.f16.f16.f32 "
        "{%0,%1,%2,%3}, {%4,%5,%6,%7}, {%8,%9}, {%0,%1,%2,%3};"
        : "+f"(d[0]), "+f"(d[1]), "+f"(d[2]), "+f"(d[3])
        : "r"(a[0]), "r"(a[1]), "r"(a[2]), "r"(a[3]), "r"(b[0]), "r"(b[1]));
}

// Prep: fp32 -> fp16, gathered (W), rewritten chunk-major pre-swizzled.
__global__ __launch_bounds__(256) void prep_all(const float4* __restrict__ f,
                                                const float4* __restrict__ W,
                                                const int* __restrict__ date_idx) {
    size_t idx = (size_t)blockIdx.x * 256 + threadIdx.x;   // 0 .. 2*NF4-1
    float4 v;
    char* base;
    int b, row, j;
    if (idx < NF4) {
        b = (int)(idx >> 17);
        int rem = (int)(idx & 131071);
        row = rem >> 7; j = rem & 127;
        v = f[idx];
        base = (char*)g_fh;
    } else {
        size_t k = idx - NF4;
        b = (int)(k >> 17);
        int rem = (int)(k & 131071);
        row = rem >> 7; j = rem & 127;
        int d = date_idx[b];
        v = W[(size_t)d * HC4 + (size_t)rem];
        base = (char*)g_wh;
    }
    __half2 h0 = __floats2half2_rn(v.x, v.y);
    __half2 h1 = __floats2half2_rn(v.z, v.w);
    uint2 o; o.x = *(uint32_t*)&h0; o.y = *(uint32_t*)&h1;
    int chunk = j >> 4, jp = (j >> 1) & 7, half = j & 1;
    size_t off = ((((size_t)(b * 8 + chunk)) * 1024 + row) << 7)
               + ((uint32_t)(jp ^ (row & 7)) << 4) + half * 8;
    *(uint2*)(base + off) = o;
}

__device__ __forceinline__ void mbar_wait(uint32_t mb, uint32_t par) {
    uint32_t done;
    asm volatile("{\n .reg .pred p;\n mbarrier.try_wait.parity.acquire.cta.shared::cta.b64 p, [%1], %2;\n selp.b32 %0,1,0,p;\n}"
                 : "=r"(done) : "r"(mb), "r"(par) : "memory");
    if (!done) {
        asm volatile("{\n .reg .pred P1;\nWL_%=:\n mbarrier.try_wait.parity.acquire.cta.shared::cta.b64 P1, [%0], %1, 0x989680;\n @P1 bra.uni WD_%=;\n bra.uni WL_%=;\nWD_%=:\n}"
                     :: "r"(mb), "r"(par) : "memory");
    }
}

__global__ __launch_bounds__(256, 2) void gemm_main(const int* __restrict__ ts,
                                                    const int* __restrict__ date_idx,
                                                    const float* __restrict__ bias,
                                                    const float* __restrict__ pos,
                                                    float* __restrict__ out) {
    extern __shared__ char smem[];
    const uint32_t sb = s2u(smem);
    const int tid = threadIdx.x;
    const int b = blockIdx.z, t0 = blockIdx.y * BM, h0 = blockIdx.x * BN;

    const char* fbase = (const char*)g_fh + (((size_t)b * 8) * 1024 + t0) * 128;
    const char* wbase = (const char*)g_wh + (((size_t)b * 8) * 1024 + h0) * 128;

    if (tid == 0) {
        #pragma unroll
        for (int s = 0; s < NSTAGE; s++)
            asm volatile("mbarrier.init.shared.b64 [%0], 1;"
                         :: "r"(sb + SM_MBAR + s * 8) : "memory");
    }
    __syncthreads();

    auto issue = [&](int chunk) {
        const int slot = chunk % NSTAGE;
        const uint32_t mb = sb + SM_MBAR + slot * 8;
        const uint32_t stb = sb + slot * STAGE_BYTES;
        const uint64_t srcA = (uint64_t)(fbase + (size_t)chunk * (1024 * 128));
        const uint64_t srcB = (uint64_t)(wbase + (size_t)chunk * (1024 * 128));
        asm volatile("mbarrier.arrive.expect_tx.shared.b64 _, [%0], %1;"
                     :: "r"(mb), "r"((uint32_t)STAGE_BYTES) : "memory");
        asm volatile("cp.async.bulk.shared::cluster.global.mbarrier::complete_tx::bytes "
                     "[%0], [%1], %2, [%3];"
                     :: "r"(stb), "l"(srcA), "r"(16384u), "r"(mb) : "memory");
        asm volatile("cp.async.bulk.shared::cluster.global.mbarrier::complete_tx::bytes "
                     "[%0], [%1], %2, [%3];"
                     :: "r"(stb + 16384u), "l"(srcB), "r"(16384u), "r"(mb) : "memory");
    };

    if (tid == 0) { issue(0); issue(1); issue(2); }

    const int w = tid >> 5, l = tid & 31;
    const int wm = w >> 2, wn = w & 3;                    // 2x4 warps
    const int m0 = wm * 64, n0 = wn * 32;                 // warp tile 64x32
    const int g = l >> 2, c4 = l & 3;

    const uint32_t swl = 4 * (l & 7);
    const uint32_t aRow = (uint32_t)(m0 + (l & 15)) * 128;
    const uint32_t aKsel = (l >> 4) * 4;
    const uint32_t bRow0 = (uint32_t)(n0 + ((l >> 4) * 8) + (l & 7)) * 128;
    const uint32_t bKsel = ((l >> 3) & 1) * 4;

    float acc[4][4][4] = {};
    uint32_t a2[2][4][4], bf2[2][4][2];

    // fragment load for (stage base, k-step) into buffer slot
    auto load_frags = [&](uint32_t stA, int ks, int buf) {
        const uint32_t stB = stA + 16384;
        const uint32_t ak = (((uint32_t)(8 * ks) + aKsel) ^ swl) << 2;
        const uint32_t bk = (((uint32_t)(8 * ks) + bKsel) ^ swl) << 2;
        #pragma unroll
        for (int im = 0; im < 4; im++)
            ldmx4(a2[buf][im], stA + aRow + im * 2048 + ak);
        #pragma unroll
        for (int jp = 0; jp < 2; jp++) {
            uint32_t r[4];
            ldmx4(r, stB + bRow0 + jp * 2048 + bk);
            bf2[buf][2 * jp][0] = r[0]; bf2[buf][2 * jp][1] = r[1];
            bf2[buf][2 * jp + 1][0] = r[2]; bf2[buf][2 * jp + 1][1] = r[3];
        }
    };

    // prologue: stage 0 full -> load first fragments
    mbar_wait(sb + SM_MBAR, 0);
    load_frags(sb, 0, 0);

    #pragma unroll 1
    for (int i = 0; i < NCH; i++) {
        const uint32_t stA = sb + (i % NSTAGE) * STAGE_BYTES;
        #pragma unroll
        for (int ks = 0; ks < 4; ks++) {
            const int cur = ks & 1, nxt = cur ^ 1;
            if (ks < 3) {
                load_frags(stA, ks + 1, nxt);
            } else if (i + 1 < NCH) {
                const int i1 = i + 1;
                mbar_wait(sb + SM_MBAR + (i1 % NSTAGE) * 8, (uint32_t)((i1 / NSTAGE) & 1));
                load_frags(sb + (i1 % NSTAGE) * STAGE_BYTES, 0, nxt);
            }
            #pragma unroll
            for (int im = 0; im < 4; im++)
                #pragma unroll
                for (int jn = 0; jn < 4; jn++)
                    mma16816(acc[im][jn], a2[cur][im], bf2[cur][jn]);
        }
        __syncthreads();                         // all warps done reading slot i
        if (i + NSTAGE < NCH && tid == 0) issue(i + NSTAGE);
    }

    // Epilogue: (acc + bias)*32 + pos[ts[t], h]
    const int d = date_idx[b];
    const float bv = bias[d];
    #pragma unroll
    for (int im = 0; im < 4; im++) {
        const int r0 = m0 + 16 * im + g;
        const int tA = t0 + r0, tB = t0 + r0 + 8;
        const int pA = ts[b * Tt + tA];
        const int pB = ts[b * Tt + tB];
        const float* posA = pos + (size_t)pA * Hh;
        const float* posB = pos + (size_t)pB * Hh;
        float* outA = out + ((size_t)b * Tt + tA) * Hh;
        float* outB = out + ((size_t)b * Tt + tB) * Hh;
        #pragma unroll
        for (int jn = 0; jn < 4; jn++) {
            const int col = h0 + n0 + 8 * jn + 2 * c4;
            float2 pv = *(const float2*)(posA + col);
            float2 o;
            o.x = (acc[im][jn][0] + bv) * SCALE_F + pv.x;
            o.y = (acc[im][jn][1] + bv) * SCALE_F + pv.y;
            *(float2*)(outA + col) = o;
            pv = *(const float2*)(posB + col);
            o.x = (acc[im][jn][2] + bv) * SCALE_F + pv.x;
            o.y = (acc[im][jn][3] + bv) * SCALE_F + pv.y;
            *(float2*)(outB + col) = o;
        }
    }
}

extern "C" void kernel_launch(void* const* d_in, const int* in_sizes, int n_in,
                              void* d_out, int out_size) {
    const float* features = (const float*)d_in[0];
    const int*   ts       = (const int*)d_in[1];
    const int*   date_idx = (const int*)d_in[2];
    const float* W        = (const float*)d_in[3];
    const float* bias     = (const float*)d_in[4];
    const float* pos      = (const float*)d_in[5];
    float* out = (float*)d_out;

    cudaFuncSetAttribute(gemm_main, cudaFuncAttributeMaxDynamicSharedMemorySize, SM_TOTAL);

    prep_all<<<(2 * NF4) / 256, 256>>>((const float4*)features, (const float4*)W, date_idx);
    gemm_main<<<dim3(Hh / BN, Tt / BM, Bb), 256, SM_TOTAL>>>(
        ts, date_idx, bias, pos, out);
}

// round 8
// speedup vs baseline: 6.9188x; 1.0287x over previous
#include <cuda_runtime.h>
#include <cuda_fp16.h>
#include <cstdint>

// out[b,t,h] = (sum_c W[d[b],h,c]*f[b,t,c] + bias[d])*32 + pos[ts[b,t],h]
// B=32,T=1024,C=512,H=1024. fp16 mma.sync GEMM (fp32 accum), TMA bulk loads
// from pre-swizzled chunk-major scratch. 4 warps, warp tile 64x64.

#define Bb 32
#define Tt 1024
#define Cc 512
#define Hh 1024
#define SCALE_F 32.0f

#define BM 128
#define BN 128
#define BK 64                 // fp16 k per chunk (128B rows)
#define NCH (Cc/BK)           // 8
#define STAGE_BYTES 32768     // A 16K + B 16K
#define NSTAGE 3
#define SM_MBAR (NSTAGE * STAGE_BYTES)      // 98304
#define SM_TOTAL (SM_MBAR + 64)

#define NF4 4194304           // B*T*C/4   (2^22)
#define HC4 131072            // H*C/4     (2^17)

// Pre-swizzled chunk-major fp16 scratch: [b][chunk][row][128B]
__device__ __align__(128) __half g_fh[(size_t)Bb*Tt*Cc];
__device__ __align__(128) __half g_wh[(size_t)Bb*Hh*Cc];

__device__ __forceinline__ uint32_t s2u(const void* p) {
    uint32_t a;
    asm("{ .reg .u64 t; cvta.to.shared.u64 t, %1; cvt.u32.u64 %0, t; }" : "=r"(a) : "l"(p));
    return a;
}

__device__ __forceinline__ void ldmx4(uint32_t* r, uint32_t addr) {
    asm volatile("ldmatrix.sync.aligned.m8n8.x4.shared.b16 {%0,%1,%2,%3}, [%4];"
                 : "=r"(r[0]), "=r"(r[1]), "=r"(r[2]), "=r"(r[3]) : "r"(addr));
}

__device__ __forceinline__ void mma16816(float* d, const uint32_t* a, const uint32_t* b) {
    asm volatile(
        "mma.sync.aligned.m16n8k16.row.col.f32.f16.f16.f32 "
        "{%0,%1,%2,%3}, {%4,%5,%6,%7}, {%8,%9}, {%0,%1,%2,%3};"
        : "+f"(d[0]), "+f"(d[1]), "+f"(d[2]), "+f"(d[3])
        : "r"(a[0]), "r"(a[1]), "r"(a[2]), "r"(a[3]), "r"(b[0]), "r"(b[1]));
}

// Prep: fp32 -> fp16, gathered (W), rewritten chunk-major pre-swizzled.
__global__ __launch_bounds__(256) void prep_all(const float4* __restrict__ f,
                                                const float4* __restrict__ W,
                                                const int* __restrict__ date_idx) {
    size_t idx = (size_t)blockIdx.x * 256 + threadIdx.x;   // 0 .. 2*NF4-1
    float4 v;
    char* base;
    int b, row, j;
    if (idx < NF4) {
        b = (int)(idx >> 17);
        int rem = (int)(idx & 131071);
        row = rem >> 7; j = rem & 127;
        v = f[idx];
        base = (char*)g_fh;
    } else {
        size_t k = idx - NF4;
        b = (int)(k >> 17);
        int rem = (int)(k & 131071);
        row = rem >> 7; j = rem & 127;
        int d = date_idx[b];
        v = W[(size_t)d * HC4 + (size_t)rem];
        base = (char*)g_wh;
    }
    __half2 h0 = __floats2half2_rn(v.x, v.y);
    __half2 h1 = __floats2half2_rn(v.z, v.w);
    uint2 o; o.x = *(uint32_t*)&h0; o.y = *(uint32_t*)&h1;
    int chunk = j >> 4, jp = (j >> 1) & 7, half = j & 1;
    size_t off = ((((size_t)(b * 8 + chunk)) * 1024 + row) << 7)
               + ((uint32_t)(jp ^ (row & 7)) << 4) + half * 8;
    *(uint2*)(base + off) = o;
}

__device__ __forceinline__ void mbar_wait(uint32_t mb, uint32_t par) {
    uint32_t done;
    asm volatile("{\n .reg .pred p;\n mbarrier.try_wait.parity.acquire.cta.shared::cta.b64 p, [%1], %2;\n selp.b32 %0,1,0,p;\n}"
                 : "=r"(done) : "r"(mb), "r"(par) : "memory");
    if (!done) {
        asm volatile("{\n .reg .pred P1;\nWL_%=:\n mbarrier.try_wait.parity.acquire.cta.shared::cta.b64 P1, [%0], %1, 0x989680;\n @P1 bra.uni WD_%=;\n bra.uni WL_%=;\nWD_%=:\n}"
                     :: "r"(mb), "r"(par) : "memory");
    }
}

__global__ __launch_bounds__(128, 2) void gemm_main(const int* __restrict__ ts,
                                                    const int* __restrict__ date_idx,
                                                    const float* __restrict__ bias,
                                                    const float* __restrict__ pos,
                                                    float* __restrict__ out) {
    extern __shared__ char smem[];
    const uint32_t sb = s2u(smem);
    const int tid = threadIdx.x;
    const int b = blockIdx.z, t0 = blockIdx.y * BM, h0 = blockIdx.x * BN;

    const char* fbase = (const char*)g_fh + (((size_t)b * 8) * 1024 + t0) * 128;
    const char* wbase = (const char*)g_wh + (((size_t)b * 8) * 1024 + h0) * 128;

    if (tid == 0) {
        #pragma unroll
        for (int s = 0; s < NSTAGE; s++)
            asm volatile("mbarrier.init.shared.b64 [%0], 1;"
                         :: "r"(sb + SM_MBAR + s * 8) : "memory");
    }
    __syncthreads();

    auto issue = [&](int chunk) {
        const int slot = chunk % NSTAGE;
        const uint32_t mb = sb + SM_MBAR + slot * 8;
        const uint32_t stb = sb + slot * STAGE_BYTES;
        const uint64_t srcA = (uint64_t)(fbase + (size_t)chunk * (1024 * 128));
        const uint64_t srcB = (uint64_t)(wbase + (size_t)chunk * (1024 * 128));
        asm volatile("mbarrier.arrive.expect_tx.shared.b64 _, [%0], %1;"
                     :: "r"(mb), "r"((uint32_t)STAGE_BYTES) : "memory");
        asm volatile("cp.async.bulk.shared::cluster.global.mbarrier::complete_tx::bytes "
                     "[%0], [%1], %2, [%3];"
                     :: "r"(stb), "l"(srcA), "r"(16384u), "r"(mb) : "memory");
        asm volatile("cp.async.bulk.shared::cluster.global.mbarrier::complete_tx::bytes "
                     "[%0], [%1], %2, [%3];"
                     :: "r"(stb + 16384u), "l"(srcB), "r"(16384u), "r"(mb) : "memory");
    };

    if (tid == 0) { issue(0); issue(1); issue(2); }

    const int w = tid >> 5, l = tid & 31;
    const int wm = w >> 1, wn = w & 1;                    // 2x2 warps
    const int m0 = wm * 64, n0 = wn * 64;                 // warp tile 64x64
    const int g = l >> 2, c4 = l & 3;

    const uint32_t swl = 4 * (l & 7);
    const uint32_t aRow = (uint32_t)(m0 + (l & 15)) * 128;
    const uint32_t aKsel = (l >> 4) * 4;
    const uint32_t bRow0 = (uint32_t)(n0 + ((l >> 4) * 8) + (l & 7)) * 128;
    const uint32_t bKsel = ((l >> 3) & 1) * 4;

    float acc[4][8][4] = {};

    #pragma unroll 1
    for (int i = 0; i < NCH; i++) {
        mbar_wait(sb + SM_MBAR + (i % NSTAGE) * 8, (uint32_t)((i / NSTAGE) & 1));
        const uint32_t stA = sb + (i % NSTAGE) * STAGE_BYTES;
        const uint32_t stB = stA + 16384;
        #pragma unroll
        for (int ks = 0; ks < 4; ks++) {
            uint32_t a[4][4], bf[8][2];
            const uint32_t ak = (((uint32_t)(8 * ks) + aKsel) ^ swl) << 2;
            const uint32_t bk = (((uint32_t)(8 * ks) + bKsel) ^ swl) << 2;
            #pragma unroll
            for (int im = 0; im < 4; im++)
                ldmx4(a[im], stA + aRow + im * 2048 + ak);
            #pragma unroll
            for (int jp = 0; jp < 4; jp++) {
                uint32_t r[4];
                ldmx4(r, stB + bRow0 + jp * 2048 + bk);
                bf[2 * jp][0] = r[0]; bf[2 * jp][1] = r[1];
                bf[2 * jp + 1][0] = r[2]; bf[2 * jp + 1][1] = r[3];
            }
            #pragma unroll
            for (int im = 0; im < 4; im++)
                #pragma unroll
                for (int jn = 0; jn < 8; jn++)
                    mma16816(acc[im][jn], a[im], bf[jn]);
        }
        __syncthreads();                         // all warps done reading slot i
        if (i + NSTAGE < NCH && tid == 0) issue(i + NSTAGE);
    }

    // Epilogue: (acc + bias)*32 + pos[ts[t], h]
    const int d = date_idx[b];
    const float bv = bias[d];
    #pragma unroll
    for (int im = 0; im < 4; im++) {
        const int r0 = m0 + 16 * im + g;
        const int tA = t0 + r0, tB = t0 + r0 + 8;
        const int pA = ts[b * Tt + tA];
        const int pB = ts[b * Tt + tB];
        const float* posA = pos + (size_t)pA * Hh;
        const float* posB = pos + (size_t)pB * Hh;
        float* outA = out + ((size_t)b * Tt + tA) * Hh;
        float* outB = out + ((size_t)b * Tt + tB) * Hh;
        #pragma unroll
        for (int jn = 0; jn < 8; jn++) {
            const int col = h0 + n0 + 8 * jn + 2 * c4;
            float2 pv = *(const float2*)(posA + col);
            float2 o;
            o.x = (acc[im][jn][0] + bv) * SCALE_F + pv.x;
            o.y = (acc[im][jn][1] + bv) * SCALE_F + pv.y;
            *(float2*)(outA + col) = o;
            pv = *(const float2*)(posB + col);
            o.x = (acc[im][jn][2] + bv) * SCALE_F + pv.x;
            o.y = (acc[im][jn][3] + bv) * SCALE_F + pv.y;
            *(float2*)(outB + col) = o;
        }
    }
}

extern "C" void kernel_launch(void* const* d_in, const int* in_sizes, int n_in,
                              void* d_out, int out_size) {
    const float* features = (const float*)d_in[0];
    const int*   ts       = (const int*)d_in[1];
    const int*   date_idx = (const int*)d_in[2];
    const float* W        = (const float*)d_in[3];
    const float* bias     = (const float*)d_in[4];
    const float* pos      = (const float*)d_in[5];
    float* out = (float*)d_out;

    cudaFuncSetAttribute(gemm_main, cudaFuncAttributeMaxDynamicSharedMemorySize, SM_TOTAL);

    prep_all<<<(2 * NF4) / 256, 256>>>((const float4*)features, (const float4*)W, date_idx);
    gemm_main<<<dim3(Hh / BN, Tt / BM, Bb), 128, SM_TOTAL>>>(
        ts, date_idx, bias, pos, out);
}

// round 10
// speedup vs baseline: 7.1859x; 1.0386x over previous
#include <cuda_runtime.h>
#include <cuda_fp16.h>
#include <cstdint>

// out[b,t,h] = (sum_c W[d[b],h,c]*f[b,t,c] + bias[d])*32 + pos[ts[b,t],h]
// B=32,T=1024,C=512,H=1024. fp16 mma.sync GEMM (fp32 accum), TMA bulk loads
// from pre-swizzled chunk-major scratch. 4 warps x 64x64, syncthreads flow
// (R8-proven), per-warp k-step stagger, paired-store prep.

#define Bb 32
#define Tt 1024
#define Cc 512
#define Hh 1024
#define SCALE_F 32.0f

#define BM 128
#define BN 128
#define BK 64                 // fp16 k per chunk (128B rows)
#define NCH (Cc/BK)           // 8
#define STAGE_BYTES 32768     // A 16K + B 16K
#define NSTAGE 3
#define SM_MBAR (NSTAGE * STAGE_BYTES)      // 98304
#define SM_TOTAL (SM_MBAR + 64)

#define HC4 131072            // H*C/4     (2^17)
#define NPAIR_F 2097152       // B*T*C/8   (2^21)

// Pre-swizzled chunk-major fp16 scratch: [b][chunk][row][128B]
__device__ __align__(128) __half g_fh[(size_t)Bb*Tt*Cc];
__device__ __align__(128) __half g_wh[(size_t)Bb*Hh*Cc];

__device__ __forceinline__ uint32_t s2u(const void* p) {
    uint32_t a;
    asm("{ .reg .u64 t; cvta.to.shared.u64 t, %1; cvt.u32.u64 %0, t; }" : "=r"(a) : "l"(p));
    return a;
}

__device__ __forceinline__ void ldmx4(uint32_t* r, uint32_t addr) {
    asm volatile("ldmatrix.sync.aligned.m8n8.x4.shared.b16 {%0,%1,%2,%3}, [%4];"
                 : "=r"(r[0]), "=r"(r[1]), "=r"(r[2]), "=r"(r[3]) : "r"(addr));
}

__device__ __forceinline__ void mma16816(float* d, const uint32_t* a, const uint32_t* b) {
    asm volatile(
        "mma.sync.aligned.m16n8k16.row.col.f32.f16.f16.f32 "
        "{%0,%1,%2,%3}, {%4,%5,%6,%7}, {%8,%9}, {%0,%1,%2,%3};"
        : "+f"(d[0]), "+f"(d[1]), "+f"(d[2]), "+f"(d[3])
        : "r"(a[0]), "r"(a[1]), "r"(a[2]), "r"(a[3]), "r"(b[0]), "r"(b[1]));
}

__device__ __forceinline__ uint32_t cvt2(float x, float y) {
    __half2 h = __floats2half2_rn(x, y);
    return *(uint32_t*)&h;
}

// Prep: fp32 -> fp16, gathered (W), chunk-major pre-swizzled.
// Each thread handles a PAIR of float4s (one 16B dst unit -> single uint4 store).
__global__ __launch_bounds__(256) void prep_all(const float4* __restrict__ f,
                                                const float4* __restrict__ W,
                                                const int* __restrict__ date_idx) {
    size_t idx = (size_t)blockIdx.x * 256 + threadIdx.x;   // 0 .. 2*NPAIR_F-1
    float4 v0, v1;
    char* base;
    int b, row, jg;
    if (idx < NPAIR_F) {
        b = (int)(idx >> 16);
        int rem = (int)(idx & 65535);
        row = rem >> 6; jg = rem & 63;
        v0 = f[2 * idx];
        v1 = f[2 * idx + 1];
        base = (char*)g_fh;
    } else {
        size_t k = idx - NPAIR_F;
        b = (int)(k >> 16);
        int rem = (int)(k & 65535);
        row = rem >> 6; jg = rem & 63;
        int d = date_idx[b];
        v0 = W[(size_t)d * HC4 + 2 * (size_t)rem];
        v1 = W[(size_t)d * HC4 + 2 * (size_t)rem + 1];
        base = (char*)g_wh;
    }
    uint4 o;
    o.x = cvt2(v0.x, v0.y);
    o.y = cvt2(v0.z, v0.w);
    o.z = cvt2(v1.x, v1.y);
    o.w = cvt2(v1.z, v1.w);
    int chunk = jg >> 3, jp = jg & 7;
    size_t off = ((((size_t)(b * 8 + chunk)) * 1024 + row) << 7)
               + ((uint32_t)(jp ^ (row & 7)) << 4);
    *(uint4*)(base + off) = o;
}

__device__ __forceinline__ void mbar_wait(uint32_t mb, uint32_t par) {
    uint32_t done;
    asm volatile("{\n .reg .pred p;\n mbarrier.try_wait.parity.acquire.cta.shared::cta.b64 p, [%1], %2;\n selp.b32 %0,1,0,p;\n}"
                 : "=r"(done) : "r"(mb), "r"(par) : "memory");
    if (!done) {
        asm volatile("{\n .reg .pred P1;\nWL_%=:\n mbarrier.try_wait.parity.acquire.cta.shared::cta.b64 P1, [%0], %1, 0x989680;\n @P1 bra.uni WD_%=;\n bra.uni WL_%=;\nWD_%=:\n}"
                     :: "r"(mb), "r"(par) : "memory");
    }
}

__global__ __launch_bounds__(128, 2) void gemm_main(const int* __restrict__ ts,
                                                    const int* __restrict__ date_idx,
                                                    const float* __restrict__ bias,
                                                    const float* __restrict__ pos,
                                                    float* __restrict__ out) {
    extern __shared__ char smem[];
    const uint32_t sb = s2u(smem);
    const int tid = threadIdx.x;
    const int b = blockIdx.z, t0 = blockIdx.y * BM, h0 = blockIdx.x * BN;

    const char* fbase = (const char*)g_fh + (((size_t)b * 8) * 1024 + t0) * 128;
    const char* wbase = (const char*)g_wh + (((size_t)b * 8) * 1024 + h0) * 128;

    if (tid == 0) {
        #pragma unroll
        for (int s = 0; s < NSTAGE; s++)
            asm volatile("mbarrier.init.shared.b64 [%0], 1;"
                         :: "r"(sb + SM_MBAR + s * 8) : "memory");
    }
    __syncthreads();

    auto issue = [&](int chunk) {
        const int slot = chunk % NSTAGE;
        const uint32_t mb = sb + SM_MBAR + slot * 8;
        const uint32_t stb = sb + slot * STAGE_BYTES;
        const uint64_t srcA = (uint64_t)(fbase + (size_t)chunk * (1024 * 128));
        const uint64_t srcB = (uint64_t)(wbase + (size_t)chunk * (1024 * 128));
        asm volatile("mbarrier.arrive.expect_tx.shared.b64 _, [%0], %1;"
                     :: "r"(mb), "r"((uint32_t)STAGE_BYTES) : "memory");
        asm volatile("cp.async.bulk.shared::cluster.global.mbarrier::complete_tx::bytes "
                     "[%0], [%1], %2, [%3];"
                     :: "r"(stb), "l"(srcA), "r"(16384u), "r"(mb) : "memory");
        asm volatile("cp.async.bulk.shared::cluster.global.mbarrier::complete_tx::bytes "
                     "[%0], [%1], %2, [%3];"
                     :: "r"(stb + 16384u), "l"(srcB), "r"(16384u), "r"(mb) : "memory");
    };

    if (tid == 0) { issue(0); issue(1); issue(2); }

    const int w = tid >> 5, l = tid & 31;
    const int wm = w >> 1, wn = w & 1;                    // 2x2 warps
    const int m0 = wm * 64, n0 = wn * 64;                 // warp tile 64x64
    const int g = l >> 2, c4 = l & 3;

    const uint32_t swl = 4 * (l & 7);
    const uint32_t aRow = (uint32_t)(m0 + (l & 15)) * 128;
    const uint32_t aKsel = (l >> 4) * 4;
    const uint32_t bRow0 = (uint32_t)(n0 + ((l >> 4) * 8) + (l & 7)) * 128;
    const uint32_t bKsel = ((l >> 3) & 1) * 4;

    float acc[4][8][4] = {};

    #pragma unroll 1
    for (int i = 0; i < NCH; i++) {
        mbar_wait(sb + SM_MBAR + (i % NSTAGE) * 8, (uint32_t)((i / NSTAGE) & 1));
        const uint32_t stA = sb + (i % NSTAGE) * STAGE_BYTES;
        const uint32_t stB = stA + 16384;
        #pragma unroll
        for (int kk = 0; kk < 4; kk++) {
            const int ks = (kk + w) & 3;          // per-warp stagger: decorrelate
            uint32_t a[4][4], bf[8][2];           // LDSM bursts across warps
            const uint32_t ak = (((uint32_t)(8 * ks) + aKsel) ^ swl) << 2;
            const uint32_t bk = (((uint32_t)(8 * ks) + bKsel) ^ swl) << 2;
            #pragma unroll
            for (int im = 0; im < 4; im++)
                ldmx4(a[im], stA + aRow + im * 2048 + ak);
            #pragma unroll
            for (int jp = 0; jp < 4; jp++) {
                uint32_t r[4];
                ldmx4(r, stB + bRow0 + jp * 2048 + bk);
                bf[2 * jp][0] = r[0]; bf[2 * jp][1] = r[1];
                bf[2 * jp + 1][0] = r[2]; bf[2 * jp + 1][1] = r[3];
            }
            #pragma unroll
            for (int im = 0; im < 4; im++)
                #pragma unroll
                for (int jn = 0; jn < 8; jn++)
                    mma16816(acc[im][jn], a[im], bf[jn]);
        }
        __syncthreads();                         // all warps done reading slot i
        if (i + NSTAGE < NCH && tid == 0) issue(i + NSTAGE);
    }

    // Epilogue: (acc + bias)*32 + pos[ts[t], h]
    const int d = date_idx[b];
    const float bv = bias[d];
    #pragma unroll
    for (int im = 0; im < 4; im++) {
        const int r0 = m0 + 16 * im + g;
        const int tA = t0 + r0, tB = t0 + r0 + 8;
        const int pA = ts[b * Tt + tA];
        const int pB = ts[b * Tt + tB];
        const float* posA = pos + (size_t)pA * Hh;
        const float* posB = pos + (size_t)pB * Hh;
        float* outA = out + ((size_t)b * Tt + tA) * Hh;
        float* outB = out + ((size_t)b * Tt + tB) * Hh;
        #pragma unroll
        for (int jn = 0; jn < 8; jn++) {
            const int col = h0 + n0 + 8 * jn + 2 * c4;
            float2 pv = *(const float2*)(posA + col);
            float2 o;
            o.x = (acc[im][jn][0] + bv) * SCALE_F + pv.x;
            o.y = (acc[im][jn][1] + bv) * SCALE_F + pv.y;
            *(float2*)(outA + col) = o;
            pv = *(const float2*)(posB + col);
            o.x = (acc[im][jn][2] + bv) * SCALE_F + pv.x;
            o.y = (acc[im][jn][3] + bv) * SCALE_F + pv.y;
            *(float2*)(outB + col) = o;
        }
    }
}

extern "C" void kernel_launch(void* const* d_in, const int* in_sizes, int n_in,
                              void* d_out, int out_size) {
    const float* features = (const float*)d_in[0];
    const int*   ts       = (const int*)d_in[1];
    const int*   date_idx = (const int*)d_in[2];
    const float* W        = (const float*)d_in[3];
    const float* bias     = (const float*)d_in[4];
    const float* pos      = (const float*)d_in[5];
    float* out = (float*)d_out;

    cudaFuncSetAttribute(gemm_main, cudaFuncAttributeMaxDynamicSharedMemorySize, SM_TOTAL);

    prep_all<<<(2 * NPAIR_F) / 256, 256>>>((const float4*)features, (const float4*)W, date_idx);
    gemm_main<<<dim3(Hh / BN, Tt / BM, Bb), 128, SM_TOTAL>>>(
        ts, date_idx, bias, pos, out);
}

// round 11
// speedup vs baseline: 7.2884x; 1.0143x over previous
#include <cuda_runtime.h>
#include <cuda_fp16.h>
#include <cstdint>

// out[b,t,h] = (sum_c W[d[b],h,c]*f[b,t,c] + bias[d])*32 + pos[ts[b,t],h]
// B=32,T=1024,C=512,H=1024. fp16 mma.sync GEMM (fp32 accum), TMA bulk loads
// from pre-swizzled chunk-major scratch. Persistent CTAs: 3-slot TMA ring
// runs continuously across tiles; epilogue overlaps next tile's prefetch.

#define Bb 32
#define Tt 1024
#define Cc 512
#define Hh 1024
#define SCALE_F 32.0f

#define BM 128
#define BN 128
#define BK 64                 // fp16 k per chunk (128B rows)
#define NCH (Cc/BK)           // 8
#define STAGE_BYTES 32768     // A 16K + B 16K
#define NSTAGE 3
#define SM_MBAR (NSTAGE * STAGE_BYTES)      // 98304
#define SM_TOTAL (SM_MBAR + 64)

#define NTILES 2048           // 8(h) x 8(t) x 32(b)
#define GRID_P 296            // 148 SMs x 2 CTAs

#define HC4 131072            // H*C/4     (2^17)
#define NPAIR_F 2097152       // B*T*C/8   (2^21)

// Pre-swizzled chunk-major fp16 scratch: [b][chunk][row][128B]
__device__ __align__(128) __half g_fh[(size_t)Bb*Tt*Cc];
__device__ __align__(128) __half g_wh[(size_t)Bb*Hh*Cc];

__device__ __forceinline__ uint32_t s2u(const void* p) {
    uint32_t a;
    asm("{ .reg .u64 t; cvta.to.shared.u64 t, %1; cvt.u32.u64 %0, t; }" : "=r"(a) : "l"(p));
    return a;
}

__device__ __forceinline__ void ldmx4(uint32_t* r, uint32_t addr) {
    asm volatile("ldmatrix.sync.aligned.m8n8.x4.shared.b16 {%0,%1,%2,%3}, [%4];"
                 : "=r"(r[0]), "=r"(r[1]), "=r"(r[2]), "=r"(r[3]) : "r"(addr));
}

__device__ __forceinline__ void mma16816(float* d, const uint32_t* a, const uint32_t* b) {
    asm volatile(
        "mma.sync.aligned.m16n8k16.row.col.f32.f16.f16.f32 "
        "{%0,%1,%2,%3}, {%4,%5,%6,%7}, {%8,%9}, {%0,%1,%2,%3};"
        : "+f"(d[0]), "+f"(d[1]), "+f"(d[2]), "+f"(d[3])
        : "r"(a[0]), "r"(a[1]), "r"(a[2]), "r"(a[3]), "r"(b[0]), "r"(b[1]));
}

__device__ __forceinline__ uint32_t cvt2(float x, float y) {
    __half2 h = __floats2half2_rn(x, y);
    return *(uint32_t*)&h;
}

// Prep: fp32 -> fp16, gathered (W), chunk-major pre-swizzled.
// Each thread handles a PAIR of float4s (one 16B dst unit -> single uint4 store).
__global__ __launch_bounds__(256) void prep_all(const float4* __restrict__ f,
                                                const float4* __restrict__ W,
                                                const int* __restrict__ date_idx) {
    size_t idx = (size_t)blockIdx.x * 256 + threadIdx.x;   // 0 .. 2*NPAIR_F-1
    float4 v0, v1;
    char* base;
    int b, row, jg;
    if (idx < NPAIR_F) {
        b = (int)(idx >> 16);
        int rem = (int)(idx & 65535);
        row = rem >> 6; jg = rem & 63;
        v0 = f[2 * idx];
        v1 = f[2 * idx + 1];
        base = (char*)g_fh;
    } else {
        size_t k = idx - NPAIR_F;
        b = (int)(k >> 16);
        int rem = (int)(k & 65535);
        row = rem >> 6; jg = rem & 63;
        int d = date_idx[b];
        v0 = W[(size_t)d * HC4 + 2 * (size_t)rem];
        v1 = W[(size_t)d * HC4 + 2 * (size_t)rem + 1];
        base = (char*)g_wh;
    }
    uint4 o;
    o.x = cvt2(v0.x, v0.y);
    o.y = cvt2(v0.z, v0.w);
    o.z = cvt2(v1.x, v1.y);
    o.w = cvt2(v1.z, v1.w);
    int chunk = jg >> 3, jp = jg & 7;
    size_t off = ((((size_t)(b * 8 + chunk)) * 1024 + row) << 7)
               + ((uint32_t)(jp ^ (row & 7)) << 4);
    *(uint4*)(base + off) = o;
}

__device__ __forceinline__ void mbar_wait(uint32_t mb, uint32_t par) {
    uint32_t done;
    asm volatile("{\n .reg .pred p;\n mbarrier.try_wait.parity.acquire.cta.shared::cta.b64 p, [%1], %2;\n selp.b32 %0,1,0,p;\n}"
                 : "=r"(done) : "r"(mb), "r"(par) : "memory");
    if (!done) {
        asm volatile("{\n .reg .pred P1;\nWL_%=:\n mbarrier.try_wait.parity.acquire.cta.shared::cta.b64 P1, [%0], %1, 0x989680;\n @P1 bra.uni WD_%=;\n bra.uni WL_%=;\nWD_%=:\n}"
                     :: "r"(mb), "r"(par) : "memory");
    }
}

__global__ __launch_bounds__(128, 2) void gemm_main(const int* __restrict__ ts,
                                                    const int* __restrict__ date_idx,
                                                    const float* __restrict__ bias,
                                                    const float* __restrict__ pos,
                                                    float* __restrict__ out) {
    extern __shared__ char smem[];
    const uint32_t sb = s2u(smem);
    const int tid = threadIdx.x;
    const int bx = blockIdx.x;

    if (tid == 0) {
        #pragma unroll
        for (int s = 0; s < NSTAGE; s++)
            asm volatile("mbarrier.init.shared.b64 [%0], 1;"
                         :: "r"(sb + SM_MBAR + s * 8) : "memory");
    }
    __syncthreads();

    const int ntiles = (NTILES - 1 - bx) / GRID_P + 1;
    const int G = ntiles * NCH;            // flattened chunk count for this CTA

    // issue global chunk g: tile = bx + (g/8)*GRID_P, chunk = g&7
    auto issue = [&](int g) {
        const int tile = bx + (g >> 3) * GRID_P;
        const int chunk = g & 7;
        const int slot = g % NSTAGE;
        const int bb = tile >> 6;
        const int tt0 = ((tile >> 3) & 7) * BM;
        const int hh0 = (tile & 7) * BN;
        const uint32_t mb = sb + SM_MBAR + slot * 8;
        const uint32_t stb = sb + slot * STAGE_BYTES;
        const uint64_t srcA = (uint64_t)((const char*)g_fh
            + ((((size_t)bb * 8 + chunk) * 1024 + tt0) << 7));
        const uint64_t srcB = (uint64_t)((const char*)g_wh
            + ((((size_t)bb * 8 + chunk) * 1024 + hh0) << 7));
        asm volatile("mbarrier.arrive.expect_tx.shared.b64 _, [%0], %1;"
                     :: "r"(mb), "r"((uint32_t)STAGE_BYTES) : "memory");
        asm volatile("cp.async.bulk.shared::cluster.global.mbarrier::complete_tx::bytes "
                     "[%0], [%1], %2, [%3];"
                     :: "r"(stb), "l"(srcA), "r"(16384u), "r"(mb) : "memory");
        asm volatile("cp.async.bulk.shared::cluster.global.mbarrier::complete_tx::bytes "
                     "[%0], [%1], %2, [%3];"
                     :: "r"(stb + 16384u), "l"(srcB), "r"(16384u), "r"(mb) : "memory");
    };

    if (tid == 0) { issue(0); issue(1); issue(2); }

    const int w = tid >> 5, l = tid & 31;
    const int wm = w >> 1, wn = w & 1;                    // 2x2 warps
    const int m0 = wm * 64, n0 = wn * 64;                 // warp tile 64x64
    const int g4 = l >> 2, c4 = l & 3;

    const uint32_t swl = 4 * (l & 7);
    const uint32_t aRow = (uint32_t)(m0 + (l & 15)) * 128;
    const uint32_t aKsel = (l >> 4) * 4;
    const uint32_t bRow0 = (uint32_t)(n0 + ((l >> 4) * 8) + (l & 7)) * 128;
    const uint32_t bKsel = ((l >> 3) & 1) * 4;

    float acc[4][8][4] = {};

    #pragma unroll 1
    for (int g = 0; g < G; g++) {
        const int slot = g % NSTAGE;
        mbar_wait(sb + SM_MBAR + slot * 8, (uint32_t)((g / NSTAGE) & 1));
        const uint32_t stA = sb + slot * STAGE_BYTES;
        const uint32_t stB = stA + 16384;
        #pragma unroll
        for (int ks = 0; ks < 4; ks++) {
            uint32_t a[4][4], bf[8][2];
            const uint32_t ak = (((uint32_t)(8 * ks) + aKsel) ^ swl) << 2;
            const uint32_t bk = (((uint32_t)(8 * ks) + bKsel) ^ swl) << 2;
            #pragma unroll
            for (int im = 0; im < 4; im++)
                ldmx4(a[im], stA + aRow + im * 2048 + ak);
            #pragma unroll
            for (int jp = 0; jp < 4; jp++) {
                uint32_t r[4];
                ldmx4(r, stB + bRow0 + jp * 2048 + bk);
                bf[2 * jp][0] = r[0]; bf[2 * jp][1] = r[1];
                bf[2 * jp + 1][0] = r[2]; bf[2 * jp + 1][1] = r[3];
            }
            #pragma unroll
            for (int im = 0; im < 4; im++)
                #pragma unroll
                for (int jn = 0; jn < 8; jn++)
                    mma16816(acc[im][jn], a[im], bf[jn]);
        }
        __syncthreads();                         // all warps done reading slot
        if (tid == 0 && g + NSTAGE < G) issue(g + NSTAGE);

        if ((g & 7) == 7) {
            // epilogue for this tile (TMA for next tile's chunks already in flight)
            const int tile = bx + (g >> 3) * GRID_P;
            const int bb = tile >> 6;
            const int tt0 = ((tile >> 3) & 7) * BM;
            const int hh0 = (tile & 7) * BN;
            const int d = date_idx[bb];
            const float bv = bias[d];
            #pragma unroll
            for (int im = 0; im < 4; im++) {
                const int r0 = m0 + 16 * im + g4;
                const int tA = tt0 + r0, tB = tt0 + r0 + 8;
                const int pA = ts[bb * Tt + tA];
                const int pB = ts[bb * Tt + tB];
                const float* posA = pos + (size_t)pA * Hh;
                const float* posB = pos + (size_t)pB * Hh;
                float* outA = out + ((size_t)bb * Tt + tA) * Hh;
                float* outB = out + ((size_t)bb * Tt + tB) * Hh;
                #pragma unroll
                for (int jn = 0; jn < 8; jn++) {
                    const int col = hh0 + n0 + 8 * jn + 2 * c4;
                    float2 pv = *(const float2*)(posA + col);
                    float2 o;
                    o.x = (acc[im][jn][0] + bv) * SCALE_F + pv.x;
                    o.y = (acc[im][jn][1] + bv) * SCALE_F + pv.y;
                    *(float2*)(outA + col) = o;
                    pv = *(const float2*)(posB + col);
                    o.x = (acc[im][jn][2] + bv) * SCALE_F + pv.x;
                    o.y = (acc[im][jn][3] + bv) * SCALE_F + pv.y;
                    *(float2*)(outB + col) = o;
                }
            }
            #pragma unroll
            for (int im = 0; im < 4; im++)
                #pragma unroll
                for (int jn = 0; jn < 8; jn++)
                    #pragma unroll
                    for (int q = 0; q < 4; q++)
                        acc[im][jn][q] = 0.0f;
        }
    }
}

extern "C" void kernel_launch(void* const* d_in, const int* in_sizes, int n_in,
                              void* d_out, int out_size) {
    const float* features = (const float*)d_in[0];
    const int*   ts       = (const int*)d_in[1];
    const int*   date_idx = (const int*)d_in[2];
    const float* W        = (const float*)d_in[3];
    const float* bias     = (const float*)d_in[4];
    const float* pos      = (const float*)d_in[5];
    float* out = (float*)d_out;

    cudaFuncSetAttribute(gemm_main, cudaFuncAttributeMaxDynamicSharedMemorySize, SM_TOTAL);

    prep_all<<<(2 * NPAIR_F) / 256, 256>>>((const float4*)features, (const float4*)W, date_idx);
    gemm_main<<<GRID_P, 128, SM_TOTAL>>>(ts, date_idx, bias, pos, out);
}